// round 10
// baseline (speedup 1.0000x reference)
#include <cuda_runtime.h>
#include <cuda_bf16.h>
#include <math.h>
#include <stdint.h>

// Problem constants (fixed shapes: B=4, S=2048, H=1024, O=512)
#define BATCH 4
#define SEQ   2048
#define HID   1024
#define OUT   512

// ===========================================================================
// Device scratch
// ===========================================================================
__device__ float g_scores[(size_t)BATCH * SEQ * SEQ];            // 64 MB fp32
__device__ float g_lam[BATCH * SEQ];

__device__ __nv_bfloat16 g_ho_hi[(size_t)BATCH * SEQ * HID];
__device__ __nv_bfloat16 g_ho_lo[(size_t)BATCH * SEQ * HID];
__device__ __nv_bfloat16 g_hi_hi[(size_t)BATCH * SEQ * HID];
__device__ __nv_bfloat16 g_hi_lo[(size_t)BATCH * SEQ * HID];
__device__ __nv_bfloat16 g_hiT_hi[(size_t)BATCH * HID * SEQ];    // hi transposed
__device__ __nv_bfloat16 g_hiT_lo[(size_t)BATCH * HID * SEQ];
__device__ __nv_bfloat16 g_attn_hi[(size_t)BATCH * SEQ * SEQ];
__device__ __nv_bfloat16 g_attn_lo[(size_t)BATCH * SEQ * SEQ];
__device__ __nv_bfloat16 g_ct_hi[(size_t)BATCH * SEQ * HID];
__device__ __nv_bfloat16 g_ct_lo[(size_t)BATCH * SEQ * HID];
__device__ __nv_bfloat16 g_wt_hi[(size_t)OUT * HID];             // W_proj^T
__device__ __nv_bfloat16 g_wt_lo[(size_t)OUT * HID];

// ===========================================================================
// Low-level helpers (all sm_80+ PTX: compiles on compute_100)
// ===========================================================================
__device__ __forceinline__ uint32_t smem_to_u32(const void* p) {
    uint32_t a;
    asm("{ .reg .u64 t; cvta.to.shared.u64 t, %1; cvt.u32.u64 %0, t; }" : "=r"(a) : "l"(p));
    return a;
}
__device__ __forceinline__ uint32_t sw64(uint32_t o) { return o ^ ((o >> 3) & 0x30); }

__device__ __forceinline__ void cp16(uint32_t dst, const void* src) {
    asm volatile("cp.async.cg.shared.global [%0], [%1], 16;" :: "r"(dst), "l"(src));
}
#define CP_COMMIT() asm volatile("cp.async.commit_group;" ::: "memory")
#define CP_WAIT(n)  asm volatile("cp.async.wait_group %0;" :: "n"(n) : "memory")

__device__ __forceinline__ void ldsm4(uint32_t (&r)[4], uint32_t addr) {
    asm volatile("ldmatrix.sync.aligned.m8n8.x4.shared.b16 {%0,%1,%2,%3}, [%4];"
                 : "=r"(r[0]), "=r"(r[1]), "=r"(r[2]), "=r"(r[3]) : "r"(addr));
}
__device__ __forceinline__ void mma16816(float (&d)[4], const uint32_t a[4], const uint32_t b[2]) {
    asm volatile(
        "mma.sync.aligned.m16n8k16.row.col.f32.bf16.bf16.f32 "
        "{%0,%1,%2,%3},{%4,%5,%6,%7},{%8,%9},{%0,%1,%2,%3};"
        : "+f"(d[0]), "+f"(d[1]), "+f"(d[2]), "+f"(d[3])
        : "r"(a[0]), "r"(a[1]), "r"(a[2]), "r"(a[3]), "r"(b[0]), "r"(b[1]));
}

__device__ __forceinline__ uint32_t pack2bf(float a, float b) {
    __nv_bfloat162 t = __floats2bfloat162_rn(a, b);
    return *reinterpret_cast<uint32_t*>(&t);
}
__device__ __forceinline__ void split1(float x, float& hf, float& lf) {
    __nv_bfloat16 h = __float2bfloat16_rn(x);
    hf = __bfloat162float(h);
    lf = x - hf;
}

// ===========================================================================
// GEMM mainloop: CTA tile 128(M) x 256(N), BK=32, 2-stage cp.async pipeline.
// Warp tile 64x64 (8 warps = 2M x 4N): ldmatrix bytes/MAC down 33% vs 64x32,
// relieving the 128 B/cyc/SM smem crossbar. 1 CTA/SM (regs ~210).
// 3-term compensated bf16: acc += Ah*Bh + Ah*Bl + Al*Bh (fp32 accum).
// A: [128 rows, K] K-contiguous; B: [256 n-rows, K] K-contiguous.
// ===========================================================================
#define BK          32
#define A_TILE      8192                   // 128 rows x 64B
#define B_TILE      16384                  // 256 rows x 64B
#define OFF_AHI     0
#define OFF_ALO     A_TILE
#define OFF_BHI     (2 * A_TILE)
#define OFF_BLO     (2 * A_TILE + B_TILE)
#define STAGE_BYTES (2 * A_TILE + 2 * B_TILE)   // 48 KB
#define SMEM_TOTAL  (2 * STAGE_BYTES)           // 96 KB

__device__ __forceinline__ void load_stage(uint32_t smem_base, int s,
    const __nv_bfloat16* __restrict__ Ah, const __nv_bfloat16* __restrict__ Al, int ldA,
    const __nv_bfloat16* __restrict__ Bh, const __nv_bfloat16* __restrict__ Bl, int ldB,
    int k0, int tid)
{
    const uint32_t sb = smem_base + (uint32_t)s * STAGE_BYTES;
    // A tiles: 128 rows x 32 bf16 = 512 cp16 each (2 iters of 256 threads)
    #pragma unroll
    for (int i = 0; i < 2; i++) {
        const int idx = tid + i * 256;           // 0..511
        const int r = idx >> 2, c = idx & 3;
        const uint32_t so = sw64((uint32_t)((r << 6) | (c << 4)));
        const size_t ga = (size_t)r * ldA + k0 + c * 8;
        cp16(sb + OFF_AHI + so, Ah + ga);
        cp16(sb + OFF_ALO + so, Al + ga);
    }
    // B tiles: 256 rows x 32 bf16 = 1024 cp16 each (4 iters)
    #pragma unroll
    for (int i = 0; i < 4; i++) {
        const int idx = tid + i * 256;           // 0..1023
        const int r = idx >> 2, c = idx & 3;
        const uint32_t so = sw64((uint32_t)((r << 6) | (c << 4)));
        const size_t gb = (size_t)r * ldB + k0 + c * 8;
        cp16(sb + OFF_BHI + so, Bh + gb);
        cp16(sb + OFF_BLO + so, Bl + gb);
    }
}

// acc[mi][ni][4]: warp tile 64(M) x 64(N); warps: wm = wid&1 (M), wn = wid>>1 (N)
__device__ __forceinline__ void gemm_mainloop(uint32_t smem_base,
    const __nv_bfloat16* __restrict__ Ah, const __nv_bfloat16* __restrict__ Al, int ldA,
    const __nv_bfloat16* __restrict__ Bh, const __nv_bfloat16* __restrict__ Bl, int ldB,
    int nchunks, int tid, float (&acc)[4][8][4])
{
    #pragma unroll
    for (int mi = 0; mi < 4; mi++)
        #pragma unroll
        for (int ni = 0; ni < 8; ni++)
            #pragma unroll
            for (int d = 0; d < 4; d++) acc[mi][ni][d] = 0.f;

    // prologue: prefetch stage 0
    load_stage(smem_base, 0, Ah, Al, ldA, Bh, Bl, ldB, 0, tid);
    CP_COMMIT();
    CP_WAIT(0);
    __syncthreads();

    const int lane = tid & 31, wid = tid >> 5;
    const int wm = wid & 1, wn = wid >> 1;
    const int quad = lane >> 3, lrow = lane & 7;
    // per-lane ldmatrix row/col-byte (within tile), before swizzle
    const uint32_t a_term = (uint32_t)((wm * 64 + (quad & 1) * 8 + lrow) << 6) + ((quad >> 1) << 4);
    const uint32_t b_term = (uint32_t)((wn * 64 + (quad >> 1) * 8 + lrow) << 6) + ((quad & 1) << 4);

    for (int c = 0; c < nchunks; c++) {
        const uint32_t sb = smem_base + (uint32_t)(c & 1) * STAGE_BYTES;

        // prefetch chunk c+1 into the other stage; overlaps compute(c)
        const int cp = c + 1;
        if (cp < nchunks)
            load_stage(smem_base, cp & 1, Ah, Al, ldA, Bh, Bl, ldB, cp * BK, tid);
        CP_COMMIT();

        #pragma unroll
        for (int ks = 0; ks < 2; ks++) {
            const uint32_t koff = (uint32_t)ks * 32;
            uint32_t Ahf[4][4], Alf[4][4];
            #pragma unroll
            for (int mi = 0; mi < 4; mi++) {
                const uint32_t off = sw64(a_term + (uint32_t)(mi << 10) + koff);
                ldsm4(Ahf[mi], sb + OFF_AHI + off);
                ldsm4(Alf[mi], sb + OFF_ALO + off);
            }
            uint32_t Bhf[4][4], Blf[4][4];
            #pragma unroll
            for (int bi = 0; bi < 4; bi++) {
                const uint32_t off = sw64(b_term + (uint32_t)(bi << 10) + koff);
                ldsm4(Bhf[bi], sb + OFF_BHI + off);
                ldsm4(Blf[bi], sb + OFF_BLO + off);
            }
            #pragma unroll
            for (int mi = 0; mi < 4; mi++)
                #pragma unroll
                for (int ni = 0; ni < 8; ni++) {
                    const uint32_t* bh = &Bhf[ni >> 1][(ni & 1) * 2];
                    const uint32_t* bl = &Blf[ni >> 1][(ni & 1) * 2];
                    mma16816(acc[mi][ni], Ahf[mi], bh);
                    mma16816(acc[mi][ni], Ahf[mi], bl);
                    mma16816(acc[mi][ni], Alf[mi], bh);
                }
        }
        CP_WAIT(0);        // chunk c+1 landed (overlapped with the MMAs above)
        __syncthreads();
    }
}

// ===========================================================================
// GEMM 1: scores = (1/32) * ho . hi^T   per batch (M=N=2048, K=1024)
// ===========================================================================
__global__ __launch_bounds__(256, 1) void k_scores_tc()
{
    extern __shared__ __align__(1024) char smem[];
    const uint32_t smem_base = smem_to_u32(smem);
    const int tid = threadIdx.x, lane = tid & 31, wid = tid >> 5;
    const int b = blockIdx.z, m0 = blockIdx.y * 128, n0 = blockIdx.x * 256;

    const size_t ab = ((size_t)b * SEQ + m0) * HID;
    const size_t bb = ((size_t)b * SEQ + n0) * HID;
    float acc[4][8][4];
    gemm_mainloop(smem_base, g_ho_hi + ab, g_ho_lo + ab, HID,
                  g_hi_hi + bb, g_hi_lo + bb, HID, HID / BK, tid, acc);

    float* C = g_scores + (size_t)b * SEQ * SEQ;
    const int wm = wid & 1, wn = wid >> 1;
    const int g = lane >> 2, tq = lane & 3;
    #pragma unroll
    for (int mi = 0; mi < 4; mi++) {
        const int r0 = m0 + wm * 64 + mi * 16 + g;
        #pragma unroll
        for (int ni = 0; ni < 8; ni++) {
            const int col = n0 + wn * 64 + ni * 8 + tq * 2;
            float2 p;
            p.x = acc[mi][ni][0] * 0.03125f; p.y = acc[mi][ni][1] * 0.03125f;
            *reinterpret_cast<float2*>(&C[(size_t)r0 * SEQ + col]) = p;
            p.x = acc[mi][ni][2] * 0.03125f; p.y = acc[mi][ni][3] * 0.03125f;
            *reinterpret_cast<float2*>(&C[(size_t)(r0 + 8) * SEQ + col]) = p;
        }
    }
}

// ===========================================================================
// GEMM 2: attended = attn . hi (via hiT) + fused gate -> ct (bf16 hi/lo)
//   per batch: M=2048, N=1024, K=2048
// ===========================================================================
__global__ __launch_bounds__(256, 1) void k_attend_tc(const float* __restrict__ ho)
{
    extern __shared__ __align__(1024) char smem[];
    const uint32_t smem_base = smem_to_u32(smem);
    const int tid = threadIdx.x, lane = tid & 31, wid = tid >> 5;
    const int b = blockIdx.z, m0 = blockIdx.y * 128, n0 = blockIdx.x * 256;

    const size_t ab = (size_t)b * SEQ * SEQ + (size_t)m0 * SEQ;
    const size_t bb = (size_t)b * HID * SEQ + (size_t)n0 * SEQ;
    float acc[4][8][4];
    gemm_mainloop(smem_base, g_attn_hi + ab, g_attn_lo + ab, SEQ,
                  g_hiT_hi + bb, g_hiT_lo + bb, SEQ, SEQ / BK, tid, acc);

    const int wm = wid & 1, wn = wid >> 1;
    const int g = lane >> 2, tq = lane & 3;
    const float* lamB = g_lam + b * SEQ;
    #pragma unroll
    for (int mi = 0; mi < 4; mi++) {
        const int r0 = m0 + wm * 64 + mi * 16 + g;
        const int r1 = r0 + 8;
        const float l0 = lamB[r0], gl0 = 1.f - l0;
        const float l1 = lamB[r1], gl1 = 1.f - l1;
        const float* hoR0 = ho + ((size_t)b * SEQ + r0) * HID;
        const float* hoR1 = ho + ((size_t)b * SEQ + r1) * HID;
        __nv_bfloat16* CH0 = g_ct_hi + ((size_t)b * SEQ + r0) * HID;
        __nv_bfloat16* CL0 = g_ct_lo + ((size_t)b * SEQ + r0) * HID;
        __nv_bfloat16* CH1 = g_ct_hi + ((size_t)b * SEQ + r1) * HID;
        __nv_bfloat16* CL1 = g_ct_lo + ((size_t)b * SEQ + r1) * HID;
        #pragma unroll
        for (int ni = 0; ni < 8; ni++) {
            const int col = n0 + wn * 64 + ni * 8 + tq * 2;
            {
                const float2 h = *reinterpret_cast<const float2*>(&hoR0[col]);
                const float c0 = l0 * h.x + gl0 * acc[mi][ni][0];
                const float c1 = l0 * h.y + gl0 * acc[mi][ni][1];
                float h0, lo0, h1, lo1;
                split1(c0, h0, lo0); split1(c1, h1, lo1);
                *reinterpret_cast<uint32_t*>(&CH0[col]) = pack2bf(h0, h1);
                *reinterpret_cast<uint32_t*>(&CL0[col]) = pack2bf(lo0, lo1);
            }
            {
                const float2 h = *reinterpret_cast<const float2*>(&hoR1[col]);
                const float c0 = l1 * h.x + gl1 * acc[mi][ni][2];
                const float c1 = l1 * h.y + gl1 * acc[mi][ni][3];
                float h0, lo0, h1, lo1;
                split1(c0, h0, lo0); split1(c1, h1, lo1);
                *reinterpret_cast<uint32_t*>(&CH1[col]) = pack2bf(h0, h1);
                *reinterpret_cast<uint32_t*>(&CL1[col]) = pack2bf(lo0, lo1);
            }
        }
    }
}

// ===========================================================================
// GEMM 3: out = ct . W_proj + b_proj  (M=8192, N=512, K=1024)
// ===========================================================================
__global__ __launch_bounds__(256, 1) void k_proj_tc(const float* __restrict__ bp,
                                                    float* __restrict__ outp)
{
    extern __shared__ __align__(1024) char smem[];
    const uint32_t smem_base = smem_to_u32(smem);
    const int tid = threadIdx.x, lane = tid & 31, wid = tid >> 5;
    const int m0 = blockIdx.y * 128, n0 = blockIdx.x * 256;

    float acc[4][8][4];
    gemm_mainloop(smem_base, g_ct_hi + (size_t)m0 * HID, g_ct_lo + (size_t)m0 * HID, HID,
                  g_wt_hi + (size_t)n0 * HID, g_wt_lo + (size_t)n0 * HID, HID,
                  HID / BK, tid, acc);

    const int wm = wid & 1, wn = wid >> 1;
    const int g = lane >> 2, tq = lane & 3;
    #pragma unroll
    for (int mi = 0; mi < 4; mi++) {
        const int r0 = m0 + wm * 64 + mi * 16 + g;
        #pragma unroll
        for (int ni = 0; ni < 8; ni++) {
            const int col = n0 + wn * 64 + ni * 8 + tq * 2;
            const float2 bb = *reinterpret_cast<const float2*>(&bp[col]);
            float2 p;
            p.x = acc[mi][ni][0] + bb.x; p.y = acc[mi][ni][1] + bb.y;
            *reinterpret_cast<float2*>(&outp[(size_t)r0 * OUT + col]) = p;
            p.x = acc[mi][ni][2] + bb.x; p.y = acc[mi][ni][3] + bb.y;
            *reinterpret_cast<float2*>(&outp[(size_t)(r0 + 8) * OUT + col]) = p;
        }
    }
}

// ===========================================================================
// Prep kernels
// ===========================================================================
__global__ __launch_bounds__(256)
void k_split(const float* __restrict__ in, __nv_bfloat16* __restrict__ oh,
             __nv_bfloat16* __restrict__ ol, int n4)
{
    const int i = blockIdx.x * 256 + threadIdx.x;
    if (i >= n4) return;
    const float4 v = reinterpret_cast<const float4*>(in)[i];
    float h0, l0, h1, l1, h2, l2, h3, l3;
    split1(v.x, h0, l0); split1(v.y, h1, l1);
    split1(v.z, h2, l2); split1(v.w, h3, l3);
    uint2 vh, vl;
    vh.x = pack2bf(h0, h1); vh.y = pack2bf(h2, h3);
    vl.x = pack2bf(l0, l1); vl.y = pack2bf(l2, l3);
    reinterpret_cast<uint2*>(oh)[i] = vh;
    reinterpret_cast<uint2*>(ol)[i] = vl;
}

// transpose [R][C] -> [C][R] with bf16 hi/lo split (batched via blockIdx.z)
__global__ __launch_bounds__(256)
void k_trans_split(const float* __restrict__ in, __nv_bfloat16* __restrict__ oh,
                   __nv_bfloat16* __restrict__ ol, int R, int C)
{
    __shared__ float t[32][33];
    const size_t boff = (size_t)blockIdx.z * R * C;
    in += boff; oh += boff; ol += boff;
    const int r0 = blockIdx.y * 32, c0 = blockIdx.x * 32;
    const int tx = threadIdx.x & 31, ty = threadIdx.x >> 5;   // 32 x 8
    #pragma unroll
    for (int i = 0; i < 4; i++)
        t[ty + i * 8][tx] = in[(size_t)(r0 + ty + i * 8) * C + c0 + tx];
    __syncthreads();
    #pragma unroll
    for (int i = 0; i < 4; i++) {
        const float v = t[tx][ty + i * 8];
        float hf, lf;
        split1(v, hf, lf);
        const size_t oidx = (size_t)(c0 + ty + i * 8) * R + r0 + tx;
        oh[oidx] = __float2bfloat16_rn(hf);
        ol[oidx] = __float2bfloat16_rn(lf);
    }
}

// lambda gate
__global__ __launch_bounds__(256)
void k_lambda(const float* __restrict__ ho, const float* __restrict__ Wl,
              const float* __restrict__ bl)
{
    const int row = blockIdx.x;
    const int t = threadIdx.x;
    const float4 xv = reinterpret_cast<const float4*>(ho + (size_t)row * HID)[t];
    const float4 wv = reinterpret_cast<const float4*>(Wl)[t];
    float s = xv.x * wv.x + xv.y * wv.y + xv.z * wv.z + xv.w * wv.w;
    #pragma unroll
    for (int o = 16; o > 0; o >>= 1) s += __shfl_xor_sync(0xFFFFFFFFu, s, o);
    __shared__ float sm[8];
    if ((t & 31) == 0) sm[t >> 5] = s;
    __syncthreads();
    if (t == 0) {
        float tot = 0.f;
        #pragma unroll
        for (int i = 0; i < 8; i++) tot += sm[i];
        tot += bl[0];
        g_lam[row] = 1.f / (1.f + expf(-tot));
    }
}

// row softmax over fp32 scores -> bf16 hi/lo attention
__global__ __launch_bounds__(256)
void k_softmax()
{
    const float* p = g_scores + (size_t)blockIdx.x * SEQ;
    __nv_bfloat16* aH = g_attn_hi + (size_t)blockIdx.x * SEQ;
    __nv_bfloat16* aL = g_attn_lo + (size_t)blockIdx.x * SEQ;
    const int t = threadIdx.x;
    float4 v0 = reinterpret_cast<const float4*>(p)[t];
    float4 v1 = reinterpret_cast<const float4*>(p)[t + 256];

    float m = fmaxf(fmaxf(fmaxf(v0.x, v0.y), fmaxf(v0.z, v0.w)),
                    fmaxf(fmaxf(v1.x, v1.y), fmaxf(v1.z, v1.w)));
    #pragma unroll
    for (int o = 16; o > 0; o >>= 1) m = fmaxf(m, __shfl_xor_sync(0xFFFFFFFFu, m, o));
    __shared__ float sm[8];
    if ((t & 31) == 0) sm[t >> 5] = m;
    __syncthreads();
    m = sm[0];
    #pragma unroll
    for (int i = 1; i < 8; i++) m = fmaxf(m, sm[i]);
    __syncthreads();

    v0.x = expf(v0.x - m); v0.y = expf(v0.y - m);
    v0.z = expf(v0.z - m); v0.w = expf(v0.w - m);
    v1.x = expf(v1.x - m); v1.y = expf(v1.y - m);
    v1.z = expf(v1.z - m); v1.w = expf(v1.w - m);

    float s = (v0.x + v0.y + v0.z + v0.w) + (v1.x + v1.y + v1.z + v1.w);
    #pragma unroll
    for (int o = 16; o > 0; o >>= 1) s += __shfl_xor_sync(0xFFFFFFFFu, s, o);
    if ((t & 31) == 0) sm[t >> 5] = s;
    __syncthreads();
    s = sm[0];
    #pragma unroll
    for (int i = 1; i < 8; i++) s += sm[i];
    const float inv = 1.f / s;

    float h0, l0, h1, l1, h2, l2, h3, l3;
    uint2 vh, vl;
    split1(v0.x * inv, h0, l0); split1(v0.y * inv, h1, l1);
    split1(v0.z * inv, h2, l2); split1(v0.w * inv, h3, l3);
    vh.x = pack2bf(h0, h1); vh.y = pack2bf(h2, h3);
    vl.x = pack2bf(l0, l1); vl.y = pack2bf(l2, l3);
    *reinterpret_cast<uint2*>(&aH[4 * t]) = vh;
    *reinterpret_cast<uint2*>(&aL[4 * t]) = vl;

    split1(v1.x * inv, h0, l0); split1(v1.y * inv, h1, l1);
    split1(v1.z * inv, h2, l2); split1(v1.w * inv, h3, l3);
    vh.x = pack2bf(h0, h1); vh.y = pack2bf(h2, h3);
    vl.x = pack2bf(l0, l1); vl.y = pack2bf(l2, l3);
    *reinterpret_cast<uint2*>(&aH[4 * (t + 256)]) = vh;
    *reinterpret_cast<uint2*>(&aL[4 * (t + 256)]) = vl;
}

// ===========================================================================
// Launch
// ===========================================================================
extern "C" void kernel_launch(void* const* d_in, const int* in_sizes, int n_in,
                              void* d_out, int out_size)
{
    const float* ho = (const float*)d_in[0];   // [4, 2048, 1024]
    const float* hi = (const float*)d_in[1];   // [4, 2048, 1024]
    const float* Wl = (const float*)d_in[2];   // [1024, 1]
    const float* bl = (const float*)d_in[3];   // [1]
    const float* Wp = (const float*)d_in[4];   // [1024, 512]
    const float* bp = (const float*)d_in[5];   // [512]
    float* outp = (float*)d_out;               // [4, 2048, 512]

    cudaFuncSetAttribute(k_scores_tc, cudaFuncAttributeMaxDynamicSharedMemorySize, SMEM_TOTAL);
    cudaFuncSetAttribute(k_attend_tc, cudaFuncAttributeMaxDynamicSharedMemorySize, SMEM_TOTAL);
    cudaFuncSetAttribute(k_proj_tc,   cudaFuncAttributeMaxDynamicSharedMemorySize, SMEM_TOTAL);

    __nv_bfloat16 *p_ho_hi, *p_ho_lo, *p_hi_hi, *p_hi_lo, *p_hiT_hi, *p_hiT_lo, *p_wt_hi, *p_wt_lo;
    cudaGetSymbolAddress((void**)&p_ho_hi,  g_ho_hi);
    cudaGetSymbolAddress((void**)&p_ho_lo,  g_ho_lo);
    cudaGetSymbolAddress((void**)&p_hi_hi,  g_hi_hi);
    cudaGetSymbolAddress((void**)&p_hi_lo,  g_hi_lo);
    cudaGetSymbolAddress((void**)&p_hiT_hi, g_hiT_hi);
    cudaGetSymbolAddress((void**)&p_hiT_lo, g_hiT_lo);
    cudaGetSymbolAddress((void**)&p_wt_hi,  g_wt_hi);
    cudaGetSymbolAddress((void**)&p_wt_lo,  g_wt_lo);

    const int n4 = BATCH * SEQ * HID / 4;

    // Prep: splits, transposes, gate
    k_split<<<(n4 + 255) / 256, 256>>>(ho, p_ho_hi, p_ho_lo, n4);
    k_split<<<(n4 + 255) / 256, 256>>>(hi, p_hi_hi, p_hi_lo, n4);
    {
        dim3 gt(HID / 32, SEQ / 32, BATCH);
        k_trans_split<<<gt, 256>>>(hi, p_hiT_hi, p_hiT_lo, SEQ, HID);
    }
    {
        dim3 gw(OUT / 32, HID / 32, 1);
        k_trans_split<<<gw, 256>>>(Wp, p_wt_hi, p_wt_lo, HID, OUT);
    }
    k_lambda<<<BATCH * SEQ, 256>>>(ho, Wl, bl);

    // GEMM1: scores
    {
        dim3 g(SEQ / 256, SEQ / 128, BATCH);   // 8 x 16 x 4
        k_scores_tc<<<g, 256, SMEM_TOTAL>>>();
    }
    // softmax -> bf16 attn splits
    k_softmax<<<BATCH * SEQ, 256>>>();
    // GEMM2: attend + gate -> ct splits
    {
        dim3 g(HID / 256, SEQ / 128, BATCH);   // 4 x 16 x 4
        k_attend_tc<<<g, 256, SMEM_TOTAL>>>(ho);
    }
    // GEMM3: projection + bias
    {
        dim3 g(OUT / 256, (BATCH * SEQ) / 128, 1);   // 2 x 64
        k_proj_tc<<<g, 256, SMEM_TOTAL>>>(bp, outp);
    }
}

// round 11
// speedup vs baseline: 1.5635x; 1.5635x over previous
#include <cuda_runtime.h>
#include <cuda_fp16.h>
#include <math.h>
#include <stdint.h>

// Problem constants (fixed shapes: B=4, S=2048, H=1024, O=512)
#define BATCH 4
#define SEQ   2048
#define HID   1024
#define OUT   512

// ===========================================================================
// Device scratch
// ===========================================================================
__device__ float g_scores[(size_t)BATCH * SEQ * SEQ];            // 64 MB fp32
__device__ float g_lam[BATCH * SEQ];

__device__ __half g_ho_h[(size_t)BATCH * SEQ * HID];             // A of GEMM1 (hi only)
__device__ __half g_hi_h[(size_t)BATCH * SEQ * HID];             // B of GEMM1 (hi)
__device__ __half g_hi_l[(size_t)BATCH * SEQ * HID];             // B of GEMM1 (lo)
__device__ __half g_hiT_h[(size_t)BATCH * HID * SEQ];            // B of GEMM2 (hi)
__device__ __half g_hiT_l[(size_t)BATCH * HID * SEQ];            // B of GEMM2 (lo)
__device__ __half g_attn_h[(size_t)BATCH * SEQ * SEQ];           // A of GEMM2 (hi only)
__device__ __half g_ct_h[(size_t)BATCH * SEQ * HID];             // A of GEMM3 (hi only)
__device__ __half g_wt_h[(size_t)OUT * HID];                     // B of GEMM3 (hi)
__device__ __half g_wt_l[(size_t)OUT * HID];                     // B of GEMM3 (lo)

// ===========================================================================
// Low-level helpers (all sm_80+ PTX: compiles on compute_100)
// ===========================================================================
__device__ __forceinline__ uint32_t smem_to_u32(const void* p) {
    uint32_t a;
    asm("{ .reg .u64 t; cvta.to.shared.u64 t, %1; cvt.u32.u64 %0, t; }" : "=r"(a) : "l"(p));
    return a;
}
__device__ __forceinline__ uint32_t sw64(uint32_t o) { return o ^ ((o >> 3) & 0x30); }

__device__ __forceinline__ void cp16(uint32_t dst, const void* src) {
    asm volatile("cp.async.cg.shared.global [%0], [%1], 16;" :: "r"(dst), "l"(src));
}
#define CP_COMMIT() asm volatile("cp.async.commit_group;" ::: "memory")
#define CP_WAIT(n)  asm volatile("cp.async.wait_group %0;" :: "n"(n) : "memory")

__device__ __forceinline__ void ldsm4(uint32_t (&r)[4], uint32_t addr) {
    asm volatile("ldmatrix.sync.aligned.m8n8.x4.shared.b16 {%0,%1,%2,%3}, [%4];"
                 : "=r"(r[0]), "=r"(r[1]), "=r"(r[2]), "=r"(r[3]) : "r"(addr));
}
__device__ __forceinline__ void mma16816(float (&d)[4], const uint32_t a[4], const uint32_t b[2]) {
    asm volatile(
        "mma.sync.aligned.m16n8k16.row.col.f32.f16.f16.f32 "
        "{%0,%1,%2,%3},{%4,%5,%6,%7},{%8,%9},{%0,%1,%2,%3};"
        : "+f"(d[0]), "+f"(d[1]), "+f"(d[2]), "+f"(d[3])
        : "r"(a[0]), "r"(a[1]), "r"(a[2]), "r"(a[3]), "r"(b[0]), "r"(b[1]));
}

__device__ __forceinline__ uint32_t pack2h(float a, float b) {
    __half2 t = __floats2half2_rn(a, b);
    return *reinterpret_cast<uint32_t*>(&t);
}
__device__ __forceinline__ void split1h(float x, float& hf, float& lf) {
    __half h = __float2half_rn(x);
    hf = __half2float(h);
    lf = x - hf;
}

// ===========================================================================
// GEMM mainloop: CTA tile 128(M) x 128(N), BK=32, 3-stage cp.async pipeline,
// 24 KB/stage (A_h, B_h, B_l) -> 72 KB smem, 2 CTAs/SM.
// 2-term fp16: acc += Ah*Bh + Ah*Bl  ==  Ah * B  (exact B, fp16-truncated A).
// A: [128 rows, K] K-contiguous; B: [128 n-rows, K] K-contiguous.
// ===========================================================================
#define BK          32
#define NSTAGE      3
#define TILE_BYTES  8192                   // 128 rows x 64B (32 fp16)
#define OFF_AH      0
#define OFF_BH      TILE_BYTES
#define OFF_BL      (2 * TILE_BYTES)
#define STAGE_BYTES (3 * TILE_BYTES)       // 24 KB
#define SMEM_TOTAL  (NSTAGE * STAGE_BYTES) // 72 KB

__device__ __forceinline__ void load_stage(uint32_t smem_base, int s,
    const __half* __restrict__ Ah, int ldA,
    const __half* __restrict__ Bh, const __half* __restrict__ Bl, int ldB,
    int k0, int tid)
{
    const uint32_t sb = smem_base + (uint32_t)s * STAGE_BYTES;
    #pragma unroll
    for (int i = 0; i < 2; i++) {
        const int idx = tid + i * 256;           // 0..511
        const int r = idx >> 2, c = idx & 3;     // row 0..127, 16B chunk 0..3
        const uint32_t so = sw64((uint32_t)((r << 6) | (c << 4)));
        const size_t ga = (size_t)r * ldA + k0 + c * 8;
        const size_t gb = (size_t)r * ldB + k0 + c * 8;
        cp16(sb + OFF_AH + so, Ah + ga);
        cp16(sb + OFF_BH + so, Bh + gb);
        cp16(sb + OFF_BL + so, Bl + gb);
    }
}

// acc[mi][ni][4]: warp tile 64(M) x 32(N); warps: wm = wid&1 (M), wn = wid>>1 (N)
__device__ __forceinline__ void gemm_mainloop(uint32_t smem_base,
    const __half* __restrict__ Ah, int ldA,
    const __half* __restrict__ Bh, const __half* __restrict__ Bl, int ldB,
    int nchunks, int tid, float (&acc)[4][4][4])
{
    #pragma unroll
    for (int mi = 0; mi < 4; mi++)
        #pragma unroll
        for (int ni = 0; ni < 4; ni++)
            #pragma unroll
            for (int d = 0; d < 4; d++) acc[mi][ni][d] = 0.f;

    // prologue: prefetch stages 0..NSTAGE-2
    #pragma unroll
    for (int s = 0; s < NSTAGE - 1; s++) {
        load_stage(smem_base, s, Ah, ldA, Bh, Bl, ldB, s * BK, tid);
        CP_COMMIT();
    }
    CP_WAIT(NSTAGE - 2);
    __syncthreads();

    const int lane = tid & 31, wid = tid >> 5;
    const int wm = wid & 1, wn = wid >> 1;
    const int quad = lane >> 3, lrow = lane & 7;
    // per-lane ldmatrix row/col-byte (within tile), before swizzle
    const uint32_t a_term = (uint32_t)((wm * 64 + (quad & 1) * 8 + lrow) << 6) + ((quad >> 1) << 4);
    const uint32_t b_term = (uint32_t)((wn * 32 + (quad >> 1) * 8 + lrow) << 6) + ((quad & 1) << 4);

    for (int c = 0; c < nchunks; c++) {
        const uint32_t sb = smem_base + (uint32_t)(c % NSTAGE) * STAGE_BYTES;

        // prefetch chunk c+NSTAGE-1 (stage last read at iter c-1 -> write-safe)
        const int cp = c + NSTAGE - 1;
        if (cp < nchunks)
            load_stage(smem_base, cp % NSTAGE, Ah, ldA, Bh, Bl, ldB, cp * BK, tid);
        CP_COMMIT();

        #pragma unroll
        for (int ks = 0; ks < 2; ks++) {
            const uint32_t koff = (uint32_t)ks * 32;
            uint32_t Ahf[4][4];
            #pragma unroll
            for (int mi = 0; mi < 4; mi++) {
                const uint32_t off = sw64(a_term + (uint32_t)(mi << 10) + koff);
                ldsm4(Ahf[mi], sb + OFF_AH + off);
            }
            uint32_t Bhf[2][4], Blf[2][4];
            #pragma unroll
            for (int bi = 0; bi < 2; bi++) {
                const uint32_t off = sw64(b_term + (uint32_t)(bi << 10) + koff);
                ldsm4(Bhf[bi], sb + OFF_BH + off);
                ldsm4(Blf[bi], sb + OFF_BL + off);
            }
            #pragma unroll
            for (int mi = 0; mi < 4; mi++)
                #pragma unroll
                for (int ni = 0; ni < 4; ni++) {
                    const uint32_t* bh = &Bhf[ni >> 1][(ni & 1) * 2];
                    const uint32_t* bl = &Blf[ni >> 1][(ni & 1) * 2];
                    mma16816(acc[mi][ni], Ahf[mi], bh);
                    mma16816(acc[mi][ni], Ahf[mi], bl);
                }
        }
        CP_WAIT(NSTAGE - 2);
        __syncthreads();
    }
}

// ===========================================================================
// GEMM 1: scores = (1/32) * ho . hi^T   per batch (M=N=2048, K=1024)
// ===========================================================================
__global__ __launch_bounds__(256, 2) void k_scores_tc()
{
    extern __shared__ __align__(1024) char smem[];
    const uint32_t smem_base = smem_to_u32(smem);
    const int tid = threadIdx.x, lane = tid & 31, wid = tid >> 5;
    const int b = blockIdx.z, m0 = blockIdx.y * 128, n0 = blockIdx.x * 128;

    const size_t ab = ((size_t)b * SEQ + m0) * HID;
    const size_t bb = ((size_t)b * SEQ + n0) * HID;
    float acc[4][4][4];
    gemm_mainloop(smem_base, g_ho_h + ab, HID,
                  g_hi_h + bb, g_hi_l + bb, HID, HID / BK, tid, acc);

    float* C = g_scores + (size_t)b * SEQ * SEQ;
    const int wm = wid & 1, wn = wid >> 1;
    const int g = lane >> 2, tq = lane & 3;
    #pragma unroll
    for (int mi = 0; mi < 4; mi++) {
        const int r0 = m0 + wm * 64 + mi * 16 + g;
        #pragma unroll
        for (int ni = 0; ni < 4; ni++) {
            const int col = n0 + wn * 32 + ni * 8 + tq * 2;
            float2 p;
            p.x = acc[mi][ni][0] * 0.03125f; p.y = acc[mi][ni][1] * 0.03125f;
            *reinterpret_cast<float2*>(&C[(size_t)r0 * SEQ + col]) = p;
            p.x = acc[mi][ni][2] * 0.03125f; p.y = acc[mi][ni][3] * 0.03125f;
            *reinterpret_cast<float2*>(&C[(size_t)(r0 + 8) * SEQ + col]) = p;
        }
    }
}

// ===========================================================================
// GEMM 2: attended = attn . hi (via hiT) + fused gate -> ct (fp16)
//   per batch: M=2048, N=1024, K=2048
// ===========================================================================
__global__ __launch_bounds__(256, 2) void k_attend_tc(const float* __restrict__ ho)
{
    extern __shared__ __align__(1024) char smem[];
    const uint32_t smem_base = smem_to_u32(smem);
    const int tid = threadIdx.x, lane = tid & 31, wid = tid >> 5;
    const int b = blockIdx.z, m0 = blockIdx.y * 128, n0 = blockIdx.x * 128;

    const size_t ab = (size_t)b * SEQ * SEQ + (size_t)m0 * SEQ;
    const size_t bb = (size_t)b * HID * SEQ + (size_t)n0 * SEQ;
    float acc[4][4][4];
    gemm_mainloop(smem_base, g_attn_h + ab, SEQ,
                  g_hiT_h + bb, g_hiT_l + bb, SEQ, SEQ / BK, tid, acc);

    const int wm = wid & 1, wn = wid >> 1;
    const int g = lane >> 2, tq = lane & 3;
    const float* lamB = g_lam + b * SEQ;
    #pragma unroll
    for (int mi = 0; mi < 4; mi++) {
        const int r0 = m0 + wm * 64 + mi * 16 + g;
        const int r1 = r0 + 8;
        const float l0 = lamB[r0], gl0 = 1.f - l0;
        const float l1 = lamB[r1], gl1 = 1.f - l1;
        const float* hoR0 = ho + ((size_t)b * SEQ + r0) * HID;
        const float* hoR1 = ho + ((size_t)b * SEQ + r1) * HID;
        __half* CH0 = g_ct_h + ((size_t)b * SEQ + r0) * HID;
        __half* CH1 = g_ct_h + ((size_t)b * SEQ + r1) * HID;
        #pragma unroll
        for (int ni = 0; ni < 4; ni++) {
            const int col = n0 + wn * 32 + ni * 8 + tq * 2;
            {
                const float2 h = *reinterpret_cast<const float2*>(&hoR0[col]);
                const float c0 = l0 * h.x + gl0 * acc[mi][ni][0];
                const float c1 = l0 * h.y + gl0 * acc[mi][ni][1];
                *reinterpret_cast<uint32_t*>(&CH0[col]) = pack2h(c0, c1);
            }
            {
                const float2 h = *reinterpret_cast<const float2*>(&hoR1[col]);
                const float c0 = l1 * h.x + gl1 * acc[mi][ni][2];
                const float c1 = l1 * h.y + gl1 * acc[mi][ni][3];
                *reinterpret_cast<uint32_t*>(&CH1[col]) = pack2h(c0, c1);
            }
        }
    }
}

// ===========================================================================
// GEMM 3: out = ct . W_proj + b_proj  (M=8192, N=512, K=1024)
// ===========================================================================
__global__ __launch_bounds__(256, 2) void k_proj_tc(const float* __restrict__ bp,
                                                    float* __restrict__ outp)
{
    extern __shared__ __align__(1024) char smem[];
    const uint32_t smem_base = smem_to_u32(smem);
    const int tid = threadIdx.x, lane = tid & 31, wid = tid >> 5;
    const int m0 = blockIdx.y * 128, n0 = blockIdx.x * 128;

    float acc[4][4][4];
    gemm_mainloop(smem_base, g_ct_h + (size_t)m0 * HID, HID,
                  g_wt_h + (size_t)n0 * HID, g_wt_l + (size_t)n0 * HID, HID,
                  HID / BK, tid, acc);

    const int wm = wid & 1, wn = wid >> 1;
    const int g = lane >> 2, tq = lane & 3;
    #pragma unroll
    for (int mi = 0; mi < 4; mi++) {
        const int r0 = m0 + wm * 64 + mi * 16 + g;
        #pragma unroll
        for (int ni = 0; ni < 4; ni++) {
            const int col = n0 + wn * 32 + ni * 8 + tq * 2;
            const float2 bb = *reinterpret_cast<const float2*>(&bp[col]);
            float2 p;
            p.x = acc[mi][ni][0] + bb.x; p.y = acc[mi][ni][1] + bb.y;
            *reinterpret_cast<float2*>(&outp[(size_t)r0 * OUT + col]) = p;
            p.x = acc[mi][ni][2] + bb.x; p.y = acc[mi][ni][3] + bb.y;
            *reinterpret_cast<float2*>(&outp[(size_t)(r0 + 8) * OUT + col]) = p;
        }
    }
}

// ===========================================================================
// Prep kernels
// ===========================================================================
// fp32 -> fp16 (hi only), vectorized x4
__global__ __launch_bounds__(256)
void k_half(const float* __restrict__ in, __half* __restrict__ oh, int n4)
{
    const int i = blockIdx.x * 256 + threadIdx.x;
    if (i >= n4) return;
    const float4 v = reinterpret_cast<const float4*>(in)[i];
    uint2 vh;
    vh.x = pack2h(v.x, v.y); vh.y = pack2h(v.z, v.w);
    reinterpret_cast<uint2*>(oh)[i] = vh;
}

// fp32 -> fp16 hi + lo pair
__global__ __launch_bounds__(256)
void k_split_hl(const float* __restrict__ in, __half* __restrict__ oh,
                __half* __restrict__ ol, int n4)
{
    const int i = blockIdx.x * 256 + threadIdx.x;
    if (i >= n4) return;
    const float4 v = reinterpret_cast<const float4*>(in)[i];
    float h0, l0, h1, l1, h2, l2, h3, l3;
    split1h(v.x, h0, l0); split1h(v.y, h1, l1);
    split1h(v.z, h2, l2); split1h(v.w, h3, l3);
    uint2 vh, vl;
    vh.x = pack2h(h0, h1); vh.y = pack2h(h2, h3);
    vl.x = pack2h(l0, l1); vl.y = pack2h(l2, l3);
    reinterpret_cast<uint2*>(oh)[i] = vh;
    reinterpret_cast<uint2*>(ol)[i] = vl;
}

// transpose [R][C] -> [C][R] with fp16 hi/lo split (batched via blockIdx.z)
__global__ __launch_bounds__(256)
void k_trans_split_hl(const float* __restrict__ in, __half* __restrict__ oh,
                      __half* __restrict__ ol, int R, int C)
{
    __shared__ float t[32][33];
    const size_t boff = (size_t)blockIdx.z * R * C;
    in += boff; oh += boff; ol += boff;
    const int r0 = blockIdx.y * 32, c0 = blockIdx.x * 32;
    const int tx = threadIdx.x & 31, ty = threadIdx.x >> 5;   // 32 x 8
    #pragma unroll
    for (int i = 0; i < 4; i++)
        t[ty + i * 8][tx] = in[(size_t)(r0 + ty + i * 8) * C + c0 + tx];
    __syncthreads();
    #pragma unroll
    for (int i = 0; i < 4; i++) {
        const float v = t[tx][ty + i * 8];
        float hf, lf;
        split1h(v, hf, lf);
        const size_t oidx = (size_t)(c0 + ty + i * 8) * R + r0 + tx;
        oh[oidx] = __float2half_rn(hf);
        ol[oidx] = __float2half_rn(lf);
    }
}

// lambda gate
__global__ __launch_bounds__(256)
void k_lambda(const float* __restrict__ ho, const float* __restrict__ Wl,
              const float* __restrict__ bl)
{
    const int row = blockIdx.x;
    const int t = threadIdx.x;
    const float4 xv = reinterpret_cast<const float4*>(ho + (size_t)row * HID)[t];
    const float4 wv = reinterpret_cast<const float4*>(Wl)[t];
    float s = xv.x * wv.x + xv.y * wv.y + xv.z * wv.z + xv.w * wv.w;
    #pragma unroll
    for (int o = 16; o > 0; o >>= 1) s += __shfl_xor_sync(0xFFFFFFFFu, s, o);
    __shared__ float sm[8];
    if ((t & 31) == 0) sm[t >> 5] = s;
    __syncthreads();
    if (t == 0) {
        float tot = 0.f;
        #pragma unroll
        for (int i = 0; i < 8; i++) tot += sm[i];
        tot += bl[0];
        g_lam[row] = 1.f / (1.f + expf(-tot));
    }
}

// row softmax over fp32 scores -> fp16 attention (hi only)
__global__ __launch_bounds__(256)
void k_softmax()
{
    const float* p = g_scores + (size_t)blockIdx.x * SEQ;
    __half* aH = g_attn_h + (size_t)blockIdx.x * SEQ;
    const int t = threadIdx.x;
    float4 v0 = reinterpret_cast<const float4*>(p)[t];
    float4 v1 = reinterpret_cast<const float4*>(p)[t + 256];

    float m = fmaxf(fmaxf(fmaxf(v0.x, v0.y), fmaxf(v0.z, v0.w)),
                    fmaxf(fmaxf(v1.x, v1.y), fmaxf(v1.z, v1.w)));
    #pragma unroll
    for (int o = 16; o > 0; o >>= 1) m = fmaxf(m, __shfl_xor_sync(0xFFFFFFFFu, m, o));
    __shared__ float sm[8];
    if ((t & 31) == 0) sm[t >> 5] = m;
    __syncthreads();
    m = sm[0];
    #pragma unroll
    for (int i = 1; i < 8; i++) m = fmaxf(m, sm[i]);
    __syncthreads();

    v0.x = expf(v0.x - m); v0.y = expf(v0.y - m);
    v0.z = expf(v0.z - m); v0.w = expf(v0.w - m);
    v1.x = expf(v1.x - m); v1.y = expf(v1.y - m);
    v1.z = expf(v1.z - m); v1.w = expf(v1.w - m);

    float s = (v0.x + v0.y + v0.z + v0.w) + (v1.x + v1.y + v1.z + v1.w);
    #pragma unroll
    for (int o = 16; o > 0; o >>= 1) s += __shfl_xor_sync(0xFFFFFFFFu, s, o);
    if ((t & 31) == 0) sm[t >> 5] = s;
    __syncthreads();
    s = sm[0];
    #pragma unroll
    for (int i = 1; i < 8; i++) s += sm[i];
    const float inv = 1.f / s;

    uint2 vh;
    vh.x = pack2h(v0.x * inv, v0.y * inv);
    vh.y = pack2h(v0.z * inv, v0.w * inv);
    *reinterpret_cast<uint2*>(&aH[4 * t]) = vh;
    vh.x = pack2h(v1.x * inv, v1.y * inv);
    vh.y = pack2h(v1.z * inv, v1.w * inv);
    *reinterpret_cast<uint2*>(&aH[4 * (t + 256)]) = vh;
}

// ===========================================================================
// Launch
// ===========================================================================
extern "C" void kernel_launch(void* const* d_in, const int* in_sizes, int n_in,
                              void* d_out, int out_size)
{
    const float* ho = (const float*)d_in[0];   // [4, 2048, 1024]
    const float* hi = (const float*)d_in[1];   // [4, 2048, 1024]
    const float* Wl = (const float*)d_in[2];   // [1024, 1]
    const float* bl = (const float*)d_in[3];   // [1]
    const float* Wp = (const float*)d_in[4];   // [1024, 512]
    const float* bp = (const float*)d_in[5];   // [512]
    float* outp = (float*)d_out;               // [4, 2048, 512]

    cudaFuncSetAttribute(k_scores_tc, cudaFuncAttributeMaxDynamicSharedMemorySize, SMEM_TOTAL);
    cudaFuncSetAttribute(k_attend_tc, cudaFuncAttributeMaxDynamicSharedMemorySize, SMEM_TOTAL);
    cudaFuncSetAttribute(k_proj_tc,   cudaFuncAttributeMaxDynamicSharedMemorySize, SMEM_TOTAL);

    __half *p_ho_h, *p_hi_h, *p_hi_l, *p_hiT_h, *p_hiT_l, *p_wt_h, *p_wt_l;
    cudaGetSymbolAddress((void**)&p_ho_h,  g_ho_h);
    cudaGetSymbolAddress((void**)&p_hi_h,  g_hi_h);
    cudaGetSymbolAddress((void**)&p_hi_l,  g_hi_l);
    cudaGetSymbolAddress((void**)&p_hiT_h, g_hiT_h);
    cudaGetSymbolAddress((void**)&p_hiT_l, g_hiT_l);
    cudaGetSymbolAddress((void**)&p_wt_h,  g_wt_h);
    cudaGetSymbolAddress((void**)&p_wt_l,  g_wt_l);

    const int n4 = BATCH * SEQ * HID / 4;

    // Prep: converts/splits, transposes, gate
    k_half<<<(n4 + 255) / 256, 256>>>(ho, p_ho_h, n4);
    k_split_hl<<<(n4 + 255) / 256, 256>>>(hi, p_hi_h, p_hi_l, n4);
    {
        dim3 gt(HID / 32, SEQ / 32, BATCH);
        k_trans_split_hl<<<gt, 256>>>(hi, p_hiT_h, p_hiT_l, SEQ, HID);
    }
    {
        dim3 gw(OUT / 32, HID / 32, 1);
        k_trans_split_hl<<<gw, 256>>>(Wp, p_wt_h, p_wt_l, HID, OUT);
    }
    k_lambda<<<BATCH * SEQ, 256>>>(ho, Wl, bl);

    // GEMM1: scores
    {
        dim3 g(SEQ / 128, SEQ / 128, BATCH);   // 16 x 16 x 4
        k_scores_tc<<<g, 256, SMEM_TOTAL>>>();
    }
    // softmax -> fp16 attn
    k_softmax<<<BATCH * SEQ, 256>>>();
    // GEMM2: attend + gate -> ct (fp16)
    {
        dim3 g(HID / 128, SEQ / 128, BATCH);   // 8 x 16 x 4
        k_attend_tc<<<g, 256, SMEM_TOTAL>>>(ho);
    }
    // GEMM3: projection + bias
    {
        dim3 g(OUT / 128, (BATCH * SEQ) / 128, 1);   // 4 x 64
        k_proj_tc<<<g, 256, SMEM_TOTAL>>>(bp, outp);
    }
}

// round 12
// speedup vs baseline: 2.5276x; 1.6166x over previous
#include <cuda_runtime.h>
#include <cuda_fp16.h>
#include <math.h>
#include <stdint.h>

// Problem constants (fixed shapes: B=4, S=2048, H=1024, O=512)
#define BATCH 4
#define SEQ   2048
#define HID   1024
#define OUT   512

// ===========================================================================
// Device scratch
// ===========================================================================
__device__ float g_scores[(size_t)BATCH * SEQ * SEQ];            // 64 MB fp32
__device__ float g_lam[BATCH * SEQ];

__device__ __half g_ho_h[(size_t)BATCH * SEQ * HID];             // A of GEMM1
__device__ __half g_hi_h[(size_t)BATCH * SEQ * HID];             // B of GEMM1
__device__ __half g_hiT_h[(size_t)BATCH * HID * SEQ];            // B of GEMM2
__device__ __half g_attn_h[(size_t)BATCH * SEQ * SEQ];           // A of GEMM2
__device__ __half g_ct_h[(size_t)BATCH * SEQ * HID];             // A of GEMM3
__device__ __half g_wt_h[(size_t)OUT * HID];                     // B of GEMM3

// ===========================================================================
// Low-level helpers (all sm_80+ PTX: compiles on compute_100)
// ===========================================================================
__device__ __forceinline__ uint32_t smem_to_u32(const void* p) {
    uint32_t a;
    asm("{ .reg .u64 t; cvta.to.shared.u64 t, %1; cvt.u32.u64 %0, t; }" : "=r"(a) : "l"(p));
    return a;
}
__device__ __forceinline__ uint32_t sw64(uint32_t o) { return o ^ ((o >> 3) & 0x30); }

__device__ __forceinline__ void cp16(uint32_t dst, const void* src) {
    asm volatile("cp.async.cg.shared.global [%0], [%1], 16;" :: "r"(dst), "l"(src));
}
#define CP_COMMIT() asm volatile("cp.async.commit_group;" ::: "memory")
#define CP_WAIT(n)  asm volatile("cp.async.wait_group %0;" :: "n"(n) : "memory")

__device__ __forceinline__ void ldsm4(uint32_t (&r)[4], uint32_t addr) {
    asm volatile("ldmatrix.sync.aligned.m8n8.x4.shared.b16 {%0,%1,%2,%3}, [%4];"
                 : "=r"(r[0]), "=r"(r[1]), "=r"(r[2]), "=r"(r[3]) : "r"(addr));
}
__device__ __forceinline__ void mma16816(float (&d)[4], const uint32_t a[4], const uint32_t b[2]) {
    asm volatile(
        "mma.sync.aligned.m16n8k16.row.col.f32.f16.f16.f32 "
        "{%0,%1,%2,%3},{%4,%5,%6,%7},{%8,%9},{%0,%1,%2,%3};"
        : "+f"(d[0]), "+f"(d[1]), "+f"(d[2]), "+f"(d[3])
        : "r"(a[0]), "r"(a[1]), "r"(a[2]), "r"(a[3]), "r"(b[0]), "r"(b[1]));
}

__device__ __forceinline__ uint32_t pack2h(float a, float b) {
    __half2 t = __floats2half2_rn(a, b);
    return *reinterpret_cast<uint32_t*>(&t);
}

// ===========================================================================
// GEMM mainloop: CTA tile 128(M) x 128(N), BK=32, 4-stage cp.async pipeline,
// 16 KB/stage (A_h, B_h) -> 64 KB smem, 2 CTAs/SM.
// Plain fp16 MMA, fp32 accum.
// A: [128 rows, K] K-contiguous; B: [128 n-rows, K] K-contiguous.
// ===========================================================================
#define BK          32
#define NSTAGE      4
#define TILE_BYTES  8192                   // 128 rows x 64B (32 fp16)
#define OFF_AH      0
#define OFF_BH      TILE_BYTES
#define STAGE_BYTES (2 * TILE_BYTES)       // 16 KB
#define SMEM_TOTAL  (NSTAGE * STAGE_BYTES) // 64 KB

__device__ __forceinline__ void load_stage(uint32_t smem_base, int s,
    const __half* __restrict__ Ah, int ldA,
    const __half* __restrict__ Bh, int ldB,
    int k0, int tid)
{
    const uint32_t sb = smem_base + (uint32_t)s * STAGE_BYTES;
    #pragma unroll
    for (int i = 0; i < 2; i++) {
        const int idx = tid + i * 256;           // 0..511
        const int r = idx >> 2, c = idx & 3;     // row 0..127, 16B chunk 0..3
        const uint32_t so = sw64((uint32_t)((r << 6) | (c << 4)));
        cp16(sb + OFF_AH + so, Ah + (size_t)r * ldA + k0 + c * 8);
        cp16(sb + OFF_BH + so, Bh + (size_t)r * ldB + k0 + c * 8);
    }
}

// acc[mi][ni][4]: warp tile 64(M) x 32(N); warps: wm = wid&1 (M), wn = wid>>1 (N)
__device__ __forceinline__ void gemm_mainloop(uint32_t smem_base,
    const __half* __restrict__ Ah, int ldA,
    const __half* __restrict__ Bh, int ldB,
    int nchunks, int tid, float (&acc)[4][4][4])
{
    #pragma unroll
    for (int mi = 0; mi < 4; mi++)
        #pragma unroll
        for (int ni = 0; ni < 4; ni++)
            #pragma unroll
            for (int d = 0; d < 4; d++) acc[mi][ni][d] = 0.f;

    // prologue: prefetch stages 0..NSTAGE-2
    #pragma unroll
    for (int s = 0; s < NSTAGE - 1; s++) {
        load_stage(smem_base, s, Ah, ldA, Bh, ldB, s * BK, tid);
        CP_COMMIT();
    }
    CP_WAIT(NSTAGE - 2);
    __syncthreads();

    const int lane = tid & 31, wid = tid >> 5;
    const int wm = wid & 1, wn = wid >> 1;
    const int quad = lane >> 3, lrow = lane & 7;
    // per-lane ldmatrix row/col-byte (within tile), before swizzle
    const uint32_t a_term = (uint32_t)((wm * 64 + (quad & 1) * 8 + lrow) << 6) + ((quad >> 1) << 4);
    const uint32_t b_term = (uint32_t)((wn * 32 + (quad >> 1) * 8 + lrow) << 6) + ((quad & 1) << 4);

    for (int c = 0; c < nchunks; c++) {
        const uint32_t sb = smem_base + (uint32_t)(c % NSTAGE) * STAGE_BYTES;

        // prefetch chunk c+NSTAGE-1 (that stage was last read at iter c-1)
        const int cp = c + NSTAGE - 1;
        if (cp < nchunks)
            load_stage(smem_base, cp % NSTAGE, Ah, ldA, Bh, ldB, cp * BK, tid);
        CP_COMMIT();

        #pragma unroll
        for (int ks = 0; ks < 2; ks++) {
            const uint32_t koff = (uint32_t)ks * 32;
            uint32_t Ahf[4][4];
            #pragma unroll
            for (int mi = 0; mi < 4; mi++) {
                const uint32_t off = sw64(a_term + (uint32_t)(mi << 10) + koff);
                ldsm4(Ahf[mi], sb + OFF_AH + off);
            }
            uint32_t Bhf[2][4];
            #pragma unroll
            for (int bi = 0; bi < 2; bi++) {
                const uint32_t off = sw64(b_term + (uint32_t)(bi << 10) + koff);
                ldsm4(Bhf[bi], sb + OFF_BH + off);
            }
            #pragma unroll
            for (int mi = 0; mi < 4; mi++)
                #pragma unroll
                for (int ni = 0; ni < 4; ni++)
                    mma16816(acc[mi][ni], Ahf[mi], &Bhf[ni >> 1][(ni & 1) * 2]);
        }
        CP_WAIT(NSTAGE - 2);   // chunk c+1 guaranteed landed
        __syncthreads();
    }
}

// ===========================================================================
// GEMM 1: scores = (1/32) * ho . hi^T   per batch (M=N=2048, K=1024)
// ===========================================================================
__global__ __launch_bounds__(256, 2) void k_scores_tc()
{
    extern __shared__ __align__(1024) char smem[];
    const uint32_t smem_base = smem_to_u32(smem);
    const int tid = threadIdx.x, lane = tid & 31, wid = tid >> 5;
    const int b = blockIdx.z, m0 = blockIdx.y * 128, n0 = blockIdx.x * 128;

    const size_t ab = ((size_t)b * SEQ + m0) * HID;
    const size_t bb = ((size_t)b * SEQ + n0) * HID;
    float acc[4][4][4];
    gemm_mainloop(smem_base, g_ho_h + ab, HID, g_hi_h + bb, HID, HID / BK, tid, acc);

    float* C = g_scores + (size_t)b * SEQ * SEQ;
    const int wm = wid & 1, wn = wid >> 1;
    const int g = lane >> 2, tq = lane & 3;
    #pragma unroll
    for (int mi = 0; mi < 4; mi++) {
        const int r0 = m0 + wm * 64 + mi * 16 + g;
        #pragma unroll
        for (int ni = 0; ni < 4; ni++) {
            const int col = n0 + wn * 32 + ni * 8 + tq * 2;
            float2 p;
            p.x = acc[mi][ni][0] * 0.03125f; p.y = acc[mi][ni][1] * 0.03125f;
            *reinterpret_cast<float2*>(&C[(size_t)r0 * SEQ + col]) = p;
            p.x = acc[mi][ni][2] * 0.03125f; p.y = acc[mi][ni][3] * 0.03125f;
            *reinterpret_cast<float2*>(&C[(size_t)(r0 + 8) * SEQ + col]) = p;
        }
    }
}

// ===========================================================================
// GEMM 2: attended = attn . hi (via hiT) + fused gate -> ct (fp16)
//   per batch: M=2048, N=1024, K=2048
// ===========================================================================
__global__ __launch_bounds__(256, 2) void k_attend_tc(const float* __restrict__ ho)
{
    extern __shared__ __align__(1024) char smem[];
    const uint32_t smem_base = smem_to_u32(smem);
    const int tid = threadIdx.x, lane = tid & 31, wid = tid >> 5;
    const int b = blockIdx.z, m0 = blockIdx.y * 128, n0 = blockIdx.x * 128;

    const size_t ab = (size_t)b * SEQ * SEQ + (size_t)m0 * SEQ;
    const size_t bb = (size_t)b * HID * SEQ + (size_t)n0 * SEQ;
    float acc[4][4][4];
    gemm_mainloop(smem_base, g_attn_h + ab, SEQ, g_hiT_h + bb, SEQ, SEQ / BK, tid, acc);

    const int wm = wid & 1, wn = wid >> 1;
    const int g = lane >> 2, tq = lane & 3;
    const float* lamB = g_lam + b * SEQ;
    #pragma unroll
    for (int mi = 0; mi < 4; mi++) {
        const int r0 = m0 + wm * 64 + mi * 16 + g;
        const int r1 = r0 + 8;
        const float l0 = lamB[r0], gl0 = 1.f - l0;
        const float l1 = lamB[r1], gl1 = 1.f - l1;
        const float* hoR0 = ho + ((size_t)b * SEQ + r0) * HID;
        const float* hoR1 = ho + ((size_t)b * SEQ + r1) * HID;
        __half* CH0 = g_ct_h + ((size_t)b * SEQ + r0) * HID;
        __half* CH1 = g_ct_h + ((size_t)b * SEQ + r1) * HID;
        #pragma unroll
        for (int ni = 0; ni < 4; ni++) {
            const int col = n0 + wn * 32 + ni * 8 + tq * 2;
            {
                const float2 h = *reinterpret_cast<const float2*>(&hoR0[col]);
                const float c0 = l0 * h.x + gl0 * acc[mi][ni][0];
                const float c1 = l0 * h.y + gl0 * acc[mi][ni][1];
                *reinterpret_cast<uint32_t*>(&CH0[col]) = pack2h(c0, c1);
            }
            {
                const float2 h = *reinterpret_cast<const float2*>(&hoR1[col]);
                const float c0 = l1 * h.x + gl1 * acc[mi][ni][2];
                const float c1 = l1 * h.y + gl1 * acc[mi][ni][3];
                *reinterpret_cast<uint32_t*>(&CH1[col]) = pack2h(c0, c1);
            }
        }
    }
}

// ===========================================================================
// GEMM 3: out = ct . W_proj + b_proj  (M=8192, N=512, K=1024)
// ===========================================================================
__global__ __launch_bounds__(256, 2) void k_proj_tc(const float* __restrict__ bp,
                                                    float* __restrict__ outp)
{
    extern __shared__ __align__(1024) char smem[];
    const uint32_t smem_base = smem_to_u32(smem);
    const int tid = threadIdx.x, lane = tid & 31, wid = tid >> 5;
    const int m0 = blockIdx.y * 128, n0 = blockIdx.x * 128;

    float acc[4][4][4];
    gemm_mainloop(smem_base, g_ct_h + (size_t)m0 * HID, HID,
                  g_wt_h + (size_t)n0 * HID, HID, HID / BK, tid, acc);

    const int wm = wid & 1, wn = wid >> 1;
    const int g = lane >> 2, tq = lane & 3;
    #pragma unroll
    for (int mi = 0; mi < 4; mi++) {
        const int r0 = m0 + wm * 64 + mi * 16 + g;
        #pragma unroll
        for (int ni = 0; ni < 4; ni++) {
            const int col = n0 + wn * 32 + ni * 8 + tq * 2;
            const float2 bb = *reinterpret_cast<const float2*>(&bp[col]);
            float2 p;
            p.x = acc[mi][ni][0] + bb.x; p.y = acc[mi][ni][1] + bb.y;
            *reinterpret_cast<float2*>(&outp[(size_t)r0 * OUT + col]) = p;
            p.x = acc[mi][ni][2] + bb.x; p.y = acc[mi][ni][3] + bb.y;
            *reinterpret_cast<float2*>(&outp[(size_t)(r0 + 8) * OUT + col]) = p;
        }
    }
}

// ===========================================================================
// Prep kernels
// ===========================================================================
// fp32 -> fp16, vectorized x4
__global__ __launch_bounds__(256)
void k_half(const float* __restrict__ in, __half* __restrict__ oh, int n4)
{
    const int i = blockIdx.x * 256 + threadIdx.x;
    if (i >= n4) return;
    const float4 v = reinterpret_cast<const float4*>(in)[i];
    uint2 vh;
    vh.x = pack2h(v.x, v.y); vh.y = pack2h(v.z, v.w);
    reinterpret_cast<uint2*>(oh)[i] = vh;
}

// transpose [R][C] -> [C][R] to fp16 (batched via blockIdx.z)
__global__ __launch_bounds__(256)
void k_trans_half(const float* __restrict__ in, __half* __restrict__ oh, int R, int C)
{
    __shared__ float t[32][33];
    const size_t boff = (size_t)blockIdx.z * R * C;
    in += boff; oh += boff;
    const int r0 = blockIdx.y * 32, c0 = blockIdx.x * 32;
    const int tx = threadIdx.x & 31, ty = threadIdx.x >> 5;   // 32 x 8
    #pragma unroll
    for (int i = 0; i < 4; i++)
        t[ty + i * 8][tx] = in[(size_t)(r0 + ty + i * 8) * C + c0 + tx];
    __syncthreads();
    #pragma unroll
    for (int i = 0; i < 4; i++) {
        const size_t oidx = (size_t)(c0 + ty + i * 8) * R + r0 + tx;
        oh[oidx] = __float2half_rn(t[tx][ty + i * 8]);
    }
}

// lambda gate
__global__ __launch_bounds__(256)
void k_lambda(const float* __restrict__ ho, const float* __restrict__ Wl,
              const float* __restrict__ bl)
{
    const int row = blockIdx.x;
    const int t = threadIdx.x;
    const float4 xv = reinterpret_cast<const float4*>(ho + (size_t)row * HID)[t];
    const float4 wv = reinterpret_cast<const float4*>(Wl)[t];
    float s = xv.x * wv.x + xv.y * wv.y + xv.z * wv.z + xv.w * wv.w;
    #pragma unroll
    for (int o = 16; o > 0; o >>= 1) s += __shfl_xor_sync(0xFFFFFFFFu, s, o);
    __shared__ float sm[8];
    if ((t & 31) == 0) sm[t >> 5] = s;
    __syncthreads();
    if (t == 0) {
        float tot = 0.f;
        #pragma unroll
        for (int i = 0; i < 8; i++) tot += sm[i];
        tot += bl[0];
        g_lam[row] = 1.f / (1.f + expf(-tot));
    }
}

// row softmax over fp32 scores -> fp16 attention
__global__ __launch_bounds__(256)
void k_softmax()
{
    const float* p = g_scores + (size_t)blockIdx.x * SEQ;
    __half* aH = g_attn_h + (size_t)blockIdx.x * SEQ;
    const int t = threadIdx.x;
    float4 v0 = reinterpret_cast<const float4*>(p)[t];
    float4 v1 = reinterpret_cast<const float4*>(p)[t + 256];

    float m = fmaxf(fmaxf(fmaxf(v0.x, v0.y), fmaxf(v0.z, v0.w)),
                    fmaxf(fmaxf(v1.x, v1.y), fmaxf(v1.z, v1.w)));
    #pragma unroll
    for (int o = 16; o > 0; o >>= 1) m = fmaxf(m, __shfl_xor_sync(0xFFFFFFFFu, m, o));
    __shared__ float sm[8];
    if ((t & 31) == 0) sm[t >> 5] = m;
    __syncthreads();
    m = sm[0];
    #pragma unroll
    for (int i = 1; i < 8; i++) m = fmaxf(m, sm[i]);
    __syncthreads();

    v0.x = expf(v0.x - m); v0.y = expf(v0.y - m);
    v0.z = expf(v0.z - m); v0.w = expf(v0.w - m);
    v1.x = expf(v1.x - m); v1.y = expf(v1.y - m);
    v1.z = expf(v1.z - m); v1.w = expf(v1.w - m);

    float s = (v0.x + v0.y + v0.z + v0.w) + (v1.x + v1.y + v1.z + v1.w);
    #pragma unroll
    for (int o = 16; o > 0; o >>= 1) s += __shfl_xor_sync(0xFFFFFFFFu, s, o);
    if ((t & 31) == 0) sm[t >> 5] = s;
    __syncthreads();
    s = sm[0];
    #pragma unroll
    for (int i = 1; i < 8; i++) s += sm[i];
    const float inv = 1.f / s;

    uint2 vh;
    vh.x = pack2h(v0.x * inv, v0.y * inv);
    vh.y = pack2h(v0.z * inv, v0.w * inv);
    *reinterpret_cast<uint2*>(&aH[4 * t]) = vh;
    vh.x = pack2h(v1.x * inv, v1.y * inv);
    vh.y = pack2h(v1.z * inv, v1.w * inv);
    *reinterpret_cast<uint2*>(&aH[4 * (t + 256)]) = vh;
}

// ===========================================================================
// Launch
// ===========================================================================
extern "C" void kernel_launch(void* const* d_in, const int* in_sizes, int n_in,
                              void* d_out, int out_size)
{
    const float* ho = (const float*)d_in[0];   // [4, 2048, 1024]
    const float* hi = (const float*)d_in[1];   // [4, 2048, 1024]
    const float* Wl = (const float*)d_in[2];   // [1024, 1]
    const float* bl = (const float*)d_in[3];   // [1]
    const float* Wp = (const float*)d_in[4];   // [1024, 512]
    const float* bp = (const float*)d_in[5];   // [512]
    float* outp = (float*)d_out;               // [4, 2048, 512]

    cudaFuncSetAttribute(k_scores_tc, cudaFuncAttributeMaxDynamicSharedMemorySize, SMEM_TOTAL);
    cudaFuncSetAttribute(k_attend_tc, cudaFuncAttributeMaxDynamicSharedMemorySize, SMEM_TOTAL);
    cudaFuncSetAttribute(k_proj_tc,   cudaFuncAttributeMaxDynamicSharedMemorySize, SMEM_TOTAL);

    __half *p_ho_h, *p_hi_h, *p_hiT_h, *p_wt_h;
    cudaGetSymbolAddress((void**)&p_ho_h,  g_ho_h);
    cudaGetSymbolAddress((void**)&p_hi_h,  g_hi_h);
    cudaGetSymbolAddress((void**)&p_hiT_h, g_hiT_h);
    cudaGetSymbolAddress((void**)&p_wt_h,  g_wt_h);

    const int n4 = BATCH * SEQ * HID / 4;

    // Prep: converts, transposes, gate
    k_half<<<(n4 + 255) / 256, 256>>>(ho, p_ho_h, n4);
    k_half<<<(n4 + 255) / 256, 256>>>(hi, p_hi_h, n4);
    {
        dim3 gt(HID / 32, SEQ / 32, BATCH);
        k_trans_half<<<gt, 256>>>(hi, p_hiT_h, SEQ, HID);
    }
    {
        dim3 gw(OUT / 32, HID / 32, 1);
        k_trans_half<<<gw, 256>>>(Wp, p_wt_h, HID, OUT);
    }
    k_lambda<<<BATCH * SEQ, 256>>>(ho, Wl, bl);

    // GEMM1: scores
    {
        dim3 g(SEQ / 128, SEQ / 128, BATCH);   // 16 x 16 x 4
        k_scores_tc<<<g, 256, SMEM_TOTAL>>>();
    }
    // softmax -> fp16 attn
    k_softmax<<<BATCH * SEQ, 256>>>();
    // GEMM2: attend + gate -> ct (fp16)
    {
        dim3 g(HID / 128, SEQ / 128, BATCH);   // 8 x 16 x 4
        k_attend_tc<<<g, 256, SMEM_TOTAL>>>(ho);
    }
    // GEMM3: projection + bias
    {
        dim3 g(OUT / 128, (BATCH * SEQ) / 128, 1);   // 4 x 64
        k_proj_tc<<<g, 256, SMEM_TOTAL>>>(bp, outp);
    }
}

// round 13
// speedup vs baseline: 2.6169x; 1.0354x over previous
#include <cuda_runtime.h>
#include <cuda_fp16.h>
#include <math.h>
#include <stdint.h>

// Problem constants (fixed shapes: B=4, S=2048, H=1024, O=512)
#define BATCH 4
#define SEQ   2048
#define HID   1024
#define OUT   512

// ===========================================================================
// Device scratch
// ===========================================================================
__device__ float g_scores[(size_t)BATCH * SEQ * SEQ];            // 64 MB fp32
__device__ float g_lam[BATCH * SEQ];

__device__ __half g_ho_h[(size_t)BATCH * SEQ * HID];             // A of GEMM1
__device__ __half g_hi_h[(size_t)BATCH * SEQ * HID];             // B of GEMM1
__device__ __half g_hiT_h[(size_t)BATCH * HID * SEQ];            // B of GEMM2
__device__ __half g_attn_h[(size_t)BATCH * SEQ * SEQ];           // A of GEMM2
__device__ __half g_ct_h[(size_t)BATCH * SEQ * HID];             // A of GEMM3
__device__ __half g_wt_h[(size_t)OUT * HID];                     // B of GEMM3

// ===========================================================================
// Low-level helpers (all sm_80+ PTX: compiles on compute_100)
// ===========================================================================
__device__ __forceinline__ uint32_t smem_to_u32(const void* p) {
    uint32_t a;
    asm("{ .reg .u64 t; cvta.to.shared.u64 t, %1; cvt.u32.u64 %0, t; }" : "=r"(a) : "l"(p));
    return a;
}
__device__ __forceinline__ uint32_t sw64(uint32_t o) { return o ^ ((o >> 3) & 0x30); }

__device__ __forceinline__ void cp16(uint32_t dst, const void* src) {
    asm volatile("cp.async.cg.shared.global [%0], [%1], 16;" :: "r"(dst), "l"(src));
}
#define CP_COMMIT() asm volatile("cp.async.commit_group;" ::: "memory")
#define CP_WAIT(n)  asm volatile("cp.async.wait_group %0;" :: "n"(n) : "memory")

__device__ __forceinline__ void ldsm4(uint32_t (&r)[4], uint32_t addr) {
    asm volatile("ldmatrix.sync.aligned.m8n8.x4.shared.b16 {%0,%1,%2,%3}, [%4];"
                 : "=r"(r[0]), "=r"(r[1]), "=r"(r[2]), "=r"(r[3]) : "r"(addr));
}
__device__ __forceinline__ void mma16816(float (&d)[4], const uint32_t a[4], const uint32_t b[2]) {
    asm volatile(
        "mma.sync.aligned.m16n8k16.row.col.f32.f16.f16.f32 "
        "{%0,%1,%2,%3},{%4,%5,%6,%7},{%8,%9},{%0,%1,%2,%3};"
        : "+f"(d[0]), "+f"(d[1]), "+f"(d[2]), "+f"(d[3])
        : "r"(a[0]), "r"(a[1]), "r"(a[2]), "r"(a[3]), "r"(b[0]), "r"(b[1]));
}

__device__ __forceinline__ uint32_t pack2h(float a, float b) {
    __half2 t = __floats2half2_rn(a, b);
    return *reinterpret_cast<uint32_t*>(&t);
}

// ===========================================================================
// GEMM mainloop: CTA tile 128(M) x 128(N), BK=32, 6-stage cp.async ring,
// 2 chunks per iteration -> ONE __syncthreads per 2 chunks.
// 16 KB/stage (A_h, B_h) -> 96 KB smem, 2 CTAs/SM.
// Plain fp16 MMA, fp32 accum.
// Iter structure: CP_WAIT(2); sync; prefetch c+4,c+5; compute c, c+1.
//  - WAR safe: stage (c+4)%6 == (c-2)%6 last read in prev iter, which all
//    threads finished before this iter's barrier.
//  - Visibility: chunks c, c+1 retired by the wait BEFORE the barrier.
// ===========================================================================
#define BK          32
#define NSTAGE      6
#define TILE_BYTES  8192                   // 128 rows x 64B (32 fp16)
#define OFF_AH      0
#define OFF_BH      TILE_BYTES
#define STAGE_BYTES (2 * TILE_BYTES)       // 16 KB
#define SMEM_TOTAL  (NSTAGE * STAGE_BYTES) // 96 KB

__device__ __forceinline__ void load_stage(uint32_t smem_base, int s,
    const __half* __restrict__ Ah, int ldA,
    const __half* __restrict__ Bh, int ldB,
    int k0, int tid)
{
    const uint32_t sb = smem_base + (uint32_t)s * STAGE_BYTES;
    #pragma unroll
    for (int i = 0; i < 2; i++) {
        const int idx = tid + i * 256;           // 0..511
        const int r = idx >> 2, c = idx & 3;     // row 0..127, 16B chunk 0..3
        const uint32_t so = sw64((uint32_t)((r << 6) | (c << 4)));
        cp16(sb + OFF_AH + so, Ah + (size_t)r * ldA + k0 + c * 8);
        cp16(sb + OFF_BH + so, Bh + (size_t)r * ldB + k0 + c * 8);
    }
}

// compute one 32-K chunk from a given stage
__device__ __forceinline__ void compute_chunk(uint32_t sb,
    uint32_t a_term, uint32_t b_term, float (&acc)[4][4][4])
{
    #pragma unroll
    for (int ks = 0; ks < 2; ks++) {
        const uint32_t koff = (uint32_t)ks * 32;
        uint32_t Ahf[4][4];
        #pragma unroll
        for (int mi = 0; mi < 4; mi++) {
            const uint32_t off = sw64(a_term + (uint32_t)(mi << 10) + koff);
            ldsm4(Ahf[mi], sb + OFF_AH + off);
        }
        uint32_t Bhf[2][4];
        #pragma unroll
        for (int bi = 0; bi < 2; bi++) {
            const uint32_t off = sw64(b_term + (uint32_t)(bi << 10) + koff);
            ldsm4(Bhf[bi], sb + OFF_BH + off);
        }
        #pragma unroll
        for (int mi = 0; mi < 4; mi++)
            #pragma unroll
            for (int ni = 0; ni < 4; ni++)
                mma16816(acc[mi][ni], Ahf[mi], &Bhf[ni >> 1][(ni & 1) * 2]);
    }
}

// acc[mi][ni][4]: warp tile 64(M) x 32(N); warps: wm = wid&1 (M), wn = wid>>1 (N)
__device__ __forceinline__ void gemm_mainloop(uint32_t smem_base,
    const __half* __restrict__ Ah, int ldA,
    const __half* __restrict__ Bh, int ldB,
    int nchunks, int tid, float (&acc)[4][4][4])
{
    #pragma unroll
    for (int mi = 0; mi < 4; mi++)
        #pragma unroll
        for (int ni = 0; ni < 4; ni++)
            #pragma unroll
            for (int d = 0; d < 4; d++) acc[mi][ni][d] = 0.f;

    // prologue: prefetch chunks 0..3 into stages 0..3 (4 commit groups)
    #pragma unroll
    for (int s = 0; s < 4; s++) {
        load_stage(smem_base, s, Ah, ldA, Bh, ldB, s * BK, tid);
        CP_COMMIT();
    }

    const int lane = tid & 31, wid = tid >> 5;
    const int wm = wid & 1, wn = wid >> 1;
    const int quad = lane >> 3, lrow = lane & 7;
    // per-lane ldmatrix row/col-byte (within tile), before swizzle
    const uint32_t a_term = (uint32_t)((wm * 64 + (quad & 1) * 8 + lrow) << 6) + ((quad >> 1) << 4);
    const uint32_t b_term = (uint32_t)((wn * 32 + (quad >> 1) * 8 + lrow) << 6) + ((quad & 1) << 4);

    for (int c = 0; c < nchunks; c += 2) {
        CP_WAIT(2);          // chunks c, c+1 landed (chunks c+2,c+3 may be in flight)
        __syncthreads();     // publish them; also closes readers of stages (c-2)%6,(c-1)%6

        // prefetch chunks c+4, c+5 (stages free since last iter's barrier)
        if (c + 4 < nchunks) {
            load_stage(smem_base, (c + 4) % NSTAGE, Ah, ldA, Bh, ldB, (c + 4) * BK, tid);
            CP_COMMIT();
        }
        if (c + 5 < nchunks) {
            load_stage(smem_base, (c + 5) % NSTAGE, Ah, ldA, Bh, ldB, (c + 5) * BK, tid);
            CP_COMMIT();
        }

        compute_chunk(smem_base + (uint32_t)(c % NSTAGE) * STAGE_BYTES, a_term, b_term, acc);
        compute_chunk(smem_base + (uint32_t)((c + 1) % NSTAGE) * STAGE_BYTES, a_term, b_term, acc);
    }
}

// ===========================================================================
// GEMM 1: scores = (1/32) * ho . hi^T   per batch (M=N=2048, K=1024)
// ===========================================================================
__global__ __launch_bounds__(256, 2) void k_scores_tc()
{
    extern __shared__ __align__(1024) char smem[];
    const uint32_t smem_base = smem_to_u32(smem);
    const int tid = threadIdx.x, lane = tid & 31, wid = tid >> 5;
    const int b = blockIdx.z, m0 = blockIdx.y * 128, n0 = blockIdx.x * 128;

    const size_t ab = ((size_t)b * SEQ + m0) * HID;
    const size_t bb = ((size_t)b * SEQ + n0) * HID;
    float acc[4][4][4];
    gemm_mainloop(smem_base, g_ho_h + ab, HID, g_hi_h + bb, HID, HID / BK, tid, acc);

    float* C = g_scores + (size_t)b * SEQ * SEQ;
    const int wm = wid & 1, wn = wid >> 1;
    const int g = lane >> 2, tq = lane & 3;
    #pragma unroll
    for (int mi = 0; mi < 4; mi++) {
        const int r0 = m0 + wm * 64 + mi * 16 + g;
        #pragma unroll
        for (int ni = 0; ni < 4; ni++) {
            const int col = n0 + wn * 32 + ni * 8 + tq * 2;
            float2 p;
            p.x = acc[mi][ni][0] * 0.03125f; p.y = acc[mi][ni][1] * 0.03125f;
            *reinterpret_cast<float2*>(&C[(size_t)r0 * SEQ + col]) = p;
            p.x = acc[mi][ni][2] * 0.03125f; p.y = acc[mi][ni][3] * 0.03125f;
            *reinterpret_cast<float2*>(&C[(size_t)(r0 + 8) * SEQ + col]) = p;
        }
    }
}

// ===========================================================================
// GEMM 2: attended = attn . hi (via hiT) + fused gate -> ct (fp16)
//   per batch: M=2048, N=1024, K=2048
// ===========================================================================
__global__ __launch_bounds__(256, 2) void k_attend_tc(const float* __restrict__ ho)
{
    extern __shared__ __align__(1024) char smem[];
    const uint32_t smem_base = smem_to_u32(smem);
    const int tid = threadIdx.x, lane = tid & 31, wid = tid >> 5;
    const int b = blockIdx.z, m0 = blockIdx.y * 128, n0 = blockIdx.x * 128;

    const size_t ab = (size_t)b * SEQ * SEQ + (size_t)m0 * SEQ;
    const size_t bb = (size_t)b * HID * SEQ + (size_t)n0 * SEQ;
    float acc[4][4][4];
    gemm_mainloop(smem_base, g_attn_h + ab, SEQ, g_hiT_h + bb, SEQ, SEQ / BK, tid, acc);

    const int wm = wid & 1, wn = wid >> 1;
    const int g = lane >> 2, tq = lane & 3;
    const float* lamB = g_lam + b * SEQ;
    #pragma unroll
    for (int mi = 0; mi < 4; mi++) {
        const int r0 = m0 + wm * 64 + mi * 16 + g;
        const int r1 = r0 + 8;
        const float l0 = lamB[r0], gl0 = 1.f - l0;
        const float l1 = lamB[r1], gl1 = 1.f - l1;
        const float* hoR0 = ho + ((size_t)b * SEQ + r0) * HID;
        const float* hoR1 = ho + ((size_t)b * SEQ + r1) * HID;
        __half* CH0 = g_ct_h + ((size_t)b * SEQ + r0) * HID;
        __half* CH1 = g_ct_h + ((size_t)b * SEQ + r1) * HID;
        #pragma unroll
        for (int ni = 0; ni < 4; ni++) {
            const int col = n0 + wn * 32 + ni * 8 + tq * 2;
            {
                const float2 h = *reinterpret_cast<const float2*>(&hoR0[col]);
                const float c0 = l0 * h.x + gl0 * acc[mi][ni][0];
                const float c1 = l0 * h.y + gl0 * acc[mi][ni][1];
                *reinterpret_cast<uint32_t*>(&CH0[col]) = pack2h(c0, c1);
            }
            {
                const float2 h = *reinterpret_cast<const float2*>(&hoR1[col]);
                const float c0 = l1 * h.x + gl1 * acc[mi][ni][2];
                const float c1 = l1 * h.y + gl1 * acc[mi][ni][3];
                *reinterpret_cast<uint32_t*>(&CH1[col]) = pack2h(c0, c1);
            }
        }
    }
}

// ===========================================================================
// GEMM 3: out = ct . W_proj + b_proj  (M=8192, N=512, K=1024)
// ===========================================================================
__global__ __launch_bounds__(256, 2) void k_proj_tc(const float* __restrict__ bp,
                                                    float* __restrict__ outp)
{
    extern __shared__ __align__(1024) char smem[];
    const uint32_t smem_base = smem_to_u32(smem);
    const int tid = threadIdx.x, lane = tid & 31, wid = tid >> 5;
    const int m0 = blockIdx.y * 128, n0 = blockIdx.x * 128;

    float acc[4][4][4];
    gemm_mainloop(smem_base, g_ct_h + (size_t)m0 * HID, HID,
                  g_wt_h + (size_t)n0 * HID, HID, HID / BK, tid, acc);

    const int wm = wid & 1, wn = wid >> 1;
    const int g = lane >> 2, tq = lane & 3;
    #pragma unroll
    for (int mi = 0; mi < 4; mi++) {
        const int r0 = m0 + wm * 64 + mi * 16 + g;
        #pragma unroll
        for (int ni = 0; ni < 4; ni++) {
            const int col = n0 + wn * 32 + ni * 8 + tq * 2;
            const float2 bb = *reinterpret_cast<const float2*>(&bp[col]);
            float2 p;
            p.x = acc[mi][ni][0] + bb.x; p.y = acc[mi][ni][1] + bb.y;
            *reinterpret_cast<float2*>(&outp[(size_t)r0 * OUT + col]) = p;
            p.x = acc[mi][ni][2] + bb.x; p.y = acc[mi][ni][3] + bb.y;
            *reinterpret_cast<float2*>(&outp[(size_t)(r0 + 8) * OUT + col]) = p;
        }
    }
}

// ===========================================================================
// Prep kernels (fused to read each input once)
// ===========================================================================
// ho: convert to fp16 AND compute lambda gate in one pass (one block per row)
__global__ __launch_bounds__(256)
void k_ho_prep(const float* __restrict__ ho, const float* __restrict__ Wl,
               const float* __restrict__ bl)
{
    const int row = blockIdx.x;
    const int t = threadIdx.x;
    const float4 xv = reinterpret_cast<const float4*>(ho + (size_t)row * HID)[t];
    const float4 wv = reinterpret_cast<const float4*>(Wl)[t];

    // fp16 store (coalesced, 8B per thread)
    uint2 vh;
    vh.x = pack2h(xv.x, xv.y); vh.y = pack2h(xv.z, xv.w);
    reinterpret_cast<uint2*>(g_ho_h + (size_t)row * HID)[t] = vh;

    // lambda dot product
    float s = xv.x * wv.x + xv.y * wv.y + xv.z * wv.z + xv.w * wv.w;
    #pragma unroll
    for (int o = 16; o > 0; o >>= 1) s += __shfl_xor_sync(0xFFFFFFFFu, s, o);
    __shared__ float sm[8];
    if ((t & 31) == 0) sm[t >> 5] = s;
    __syncthreads();
    if (t == 0) {
        float tot = 0.f;
        #pragma unroll
        for (int i = 0; i < 8; i++) tot += sm[i];
        tot += bl[0];
        g_lam[row] = 1.f / (1.f + expf(-tot));
    }
}

// hi: one read -> fp16 row-major (g_hi_h) AND fp16 transposed (g_hiT_h)
__global__ __launch_bounds__(256)
void k_hi_prep(const float* __restrict__ in)
{
    __shared__ float t[32][33];
    const size_t boff = (size_t)blockIdx.z * SEQ * HID;
    const float* inB = in + boff;
    __half* ohB  = g_hi_h  + boff;
    __half* otB  = g_hiT_h + boff;
    const int r0 = blockIdx.y * 32, c0 = blockIdx.x * 32;
    const int tx = threadIdx.x & 31, ty = threadIdx.x >> 5;   // 32 x 8
    #pragma unroll
    for (int i = 0; i < 4; i++) {
        const int r = r0 + ty + i * 8;
        const float v = inB[(size_t)r * HID + c0 + tx];
        t[ty + i * 8][tx] = v;
        ohB[(size_t)r * HID + c0 + tx] = __float2half_rn(v);
    }
    __syncthreads();
    #pragma unroll
    for (int i = 0; i < 4; i++) {
        const size_t oidx = (size_t)(c0 + ty + i * 8) * SEQ + r0 + tx;
        otB[oidx] = __float2half_rn(t[tx][ty + i * 8]);
    }
}

// transpose [R][C] -> [C][R] to fp16 (for W_proj; tiny)
__global__ __launch_bounds__(256)
void k_trans_half(const float* __restrict__ in, __half* __restrict__ oh, int R, int C)
{
    __shared__ float t[32][33];
    const int r0 = blockIdx.y * 32, c0 = blockIdx.x * 32;
    const int tx = threadIdx.x & 31, ty = threadIdx.x >> 5;   // 32 x 8
    #pragma unroll
    for (int i = 0; i < 4; i++)
        t[ty + i * 8][tx] = in[(size_t)(r0 + ty + i * 8) * C + c0 + tx];
    __syncthreads();
    #pragma unroll
    for (int i = 0; i < 4; i++) {
        const size_t oidx = (size_t)(c0 + ty + i * 8) * R + r0 + tx;
        oh[oidx] = __float2half_rn(t[tx][ty + i * 8]);
    }
}

// row softmax over fp32 scores -> fp16 attention
__global__ __launch_bounds__(256)
void k_softmax()
{
    const float* p = g_scores + (size_t)blockIdx.x * SEQ;
    __half* aH = g_attn_h + (size_t)blockIdx.x * SEQ;
    const int t = threadIdx.x;
    float4 v0 = reinterpret_cast<const float4*>(p)[t];
    float4 v1 = reinterpret_cast<const float4*>(p)[t + 256];

    float m = fmaxf(fmaxf(fmaxf(v0.x, v0.y), fmaxf(v0.z, v0.w)),
                    fmaxf(fmaxf(v1.x, v1.y), fmaxf(v1.z, v1.w)));
    #pragma unroll
    for (int o = 16; o > 0; o >>= 1) m = fmaxf(m, __shfl_xor_sync(0xFFFFFFFFu, m, o));
    __shared__ float sm[8];
    if ((t & 31) == 0) sm[t >> 5] = m;
    __syncthreads();
    m = sm[0];
    #pragma unroll
    for (int i = 1; i < 8; i++) m = fmaxf(m, sm[i]);
    __syncthreads();

    v0.x = expf(v0.x - m); v0.y = expf(v0.y - m);
    v0.z = expf(v0.z - m); v0.w = expf(v0.w - m);
    v1.x = expf(v1.x - m); v1.y = expf(v1.y - m);
    v1.z = expf(v1.z - m); v1.w = expf(v1.w - m);

    float s = (v0.x + v0.y + v0.z + v0.w) + (v1.x + v1.y + v1.z + v1.w);
    #pragma unroll
    for (int o = 16; o > 0; o >>= 1) s += __shfl_xor_sync(0xFFFFFFFFu, s, o);
    if ((t & 31) == 0) sm[t >> 5] = s;
    __syncthreads();
    s = sm[0];
    #pragma unroll
    for (int i = 1; i < 8; i++) s += sm[i];
    const float inv = 1.f / s;

    uint2 vh;
    vh.x = pack2h(v0.x * inv, v0.y * inv);
    vh.y = pack2h(v0.z * inv, v0.w * inv);
    *reinterpret_cast<uint2*>(&aH[4 * t]) = vh;
    vh.x = pack2h(v1.x * inv, v1.y * inv);
    vh.y = pack2h(v1.z * inv, v1.w * inv);
    *reinterpret_cast<uint2*>(&aH[4 * (t + 256)]) = vh;
}

// ===========================================================================
// Launch
// ===========================================================================
extern "C" void kernel_launch(void* const* d_in, const int* in_sizes, int n_in,
                              void* d_out, int out_size)
{
    const float* ho = (const float*)d_in[0];   // [4, 2048, 1024]
    const float* hi = (const float*)d_in[1];   // [4, 2048, 1024]
    const float* Wl = (const float*)d_in[2];   // [1024, 1]
    const float* bl = (const float*)d_in[3];   // [1]
    const float* Wp = (const float*)d_in[4];   // [1024, 512]
    const float* bp = (const float*)d_in[5];   // [512]
    float* outp = (float*)d_out;               // [4, 2048, 512]

    cudaFuncSetAttribute(k_scores_tc, cudaFuncAttributeMaxDynamicSharedMemorySize, SMEM_TOTAL);
    cudaFuncSetAttribute(k_attend_tc, cudaFuncAttributeMaxDynamicSharedMemorySize, SMEM_TOTAL);
    cudaFuncSetAttribute(k_proj_tc,   cudaFuncAttributeMaxDynamicSharedMemorySize, SMEM_TOTAL);

    __half* p_wt_h;
    cudaGetSymbolAddress((void**)&p_wt_h, g_wt_h);

    // Prep: fused converts/transposes/gate
    k_ho_prep<<<BATCH * SEQ, 256>>>(ho, Wl, bl);
    {
        dim3 gt(HID / 32, SEQ / 32, BATCH);
        k_hi_prep<<<gt, 256>>>(hi);
    }
    {
        dim3 gw(OUT / 32, HID / 32, 1);
        k_trans_half<<<gw, 256>>>(Wp, p_wt_h, HID, OUT);
    }

    // GEMM1: scores
    {
        dim3 g(SEQ / 128, SEQ / 128, BATCH);   // 16 x 16 x 4
        k_scores_tc<<<g, 256, SMEM_TOTAL>>>();
    }
    // softmax -> fp16 attn
    k_softmax<<<BATCH * SEQ, 256>>>();
    // GEMM2: attend + gate -> ct (fp16)
    {
        dim3 g(HID / 128, SEQ / 128, BATCH);   // 8 x 16 x 4
        k_attend_tc<<<g, 256, SMEM_TOTAL>>>(ho);
    }
    // GEMM3: projection + bias
    {
        dim3 g(OUT / 128, (BATCH * SEQ) / 128, 1);   // 4 x 64
        k_proj_tc<<<g, 256, SMEM_TOTAL>>>(bp, outp);
    }
}